// round 1
// baseline (speedup 1.0000x reference)
#include <cuda_runtime.h>

// Problem constants
#define Hc   64
#define Wc   64
#define CC   256
#define BB   4
#define OO   256
#define KKc  9
#define HWc  4096            // 64*64
#define KDIM 2304            // C*KK
#define MDIM 16384           // B*H*W

// Scratch (static device allocations — allowed)
__device__ float g_xt[BB * HWc * CC];          // x in NHWC, 16.8 MB
__device__ float g_wt[KDIM * OO];              // weight [kdim][o], 2.36 MB
__device__ float g_col[37748736];              // im2col [M][KDIM], 151 MB

// ---------------------------------------------------------------------------
// Kernel 1: NCHW -> NHWC transpose of x (per-b [C][HW] -> [HW][C])
// ---------------------------------------------------------------------------
__global__ void k_transpose(const float* __restrict__ x) {
    __shared__ float t[32][33];
    const int b  = blockIdx.z;
    const int p0 = blockIdx.x * 32;   // HW dim
    const int c0 = blockIdx.y * 32;   // C dim
    const int tx = threadIdx.x, ty = threadIdx.y;  // 32 x 8
#pragma unroll
    for (int i = 0; i < 32; i += 8)
        t[ty + i][tx] = x[(size_t)(b * CC + c0 + ty + i) * HWc + p0 + tx];
    __syncthreads();
#pragma unroll
    for (int i = 0; i < 32; i += 8)
        g_xt[(size_t)(b * HWc + p0 + ty + i) * CC + c0 + tx] = t[tx][ty + i];
}

// ---------------------------------------------------------------------------
// Kernel 2: weight [O][C][KK] -> wt[(kk*256+c)][o]
// ---------------------------------------------------------------------------
__global__ void k_wt(const float* __restrict__ w) {
    const int idx = blockIdx.x * 256 + threadIdx.x;  // over KDIM*OO
    const int o  = idx & 255;
    const int kd = idx >> 8;          // 0..2303
    const int kk = kd >> 8;           // kd / 256
    const int c  = kd & 255;
    g_wt[idx] = w[(o * CC + c) * KKc + kk];
}

// ---------------------------------------------------------------------------
// Kernel 3: bilinear-sampled, masked im2col.
// Block = 256 threads = 4 sample points x 64 lanes; each lane does 4 channels.
// sp = (b*9 + kk)*4096 + p
// col[m = b*4096+p][kk*256 + c]
// ---------------------------------------------------------------------------
__global__ void k_im2col(const float* __restrict__ off,
                         const float* __restrict__ msk) {
    const int t    = threadIdx.x;
    const int sp   = blockIdx.x * 4 + (t >> 6);
    const int lane = t & 63;

    const int p   = sp & (HWc - 1);
    const int tmp = sp >> 12;
    const int kk  = tmp % KKc;
    const int b   = tmp / KKc;
    const int ho  = p >> 6, wo = p & 63;
    const int ki  = kk / 3, kj = kk - ki * 3;

    const int obase = ((b * 2 * KKc + kk * 2) * Hc + ho) * Wc + wo;
    const float dy = off[obase];
    const float dx = off[obase + Hc * Wc];
    const float mm = msk[((b * KKc + kk) * Hc + ho) * Wc + wo];

    const float py = (float)(ho - 1 + ki) + dy;
    const float px = (float)(wo - 1 + kj) + dx;
    const float y0f = floorf(py), x0f = floorf(px);
    const int   y0 = (int)y0f,    x0 = (int)x0f;
    const float wy = py - y0f,    wx = px - x0f;

    const float w00 = (1.f - wy) * (1.f - wx);
    const float w01 = (1.f - wy) * wx;
    const float w10 = wy * (1.f - wx);
    const float w11 = wy * wx;

    const int c = lane * 4;
    float4 acc = make_float4(0.f, 0.f, 0.f, 0.f);

    const float* xb = g_xt + (size_t)b * HWc * CC;

#define GATHER(yy, xx, wgt)                                                    \
    if ((unsigned)(yy) < Hc && (unsigned)(xx) < Wc) {                          \
        const float4 v = *(const float4*)&xb[(size_t)((yy) * Wc + (xx)) * CC + c]; \
        acc.x += (wgt) * v.x; acc.y += (wgt) * v.y;                            \
        acc.z += (wgt) * v.z; acc.w += (wgt) * v.w;                            \
    }
    GATHER(y0,     x0,     w00)
    GATHER(y0,     x0 + 1, w01)
    GATHER(y0 + 1, x0,     w10)
    GATHER(y0 + 1, x0 + 1, w11)
#undef GATHER

    acc.x *= mm; acc.y *= mm; acc.z *= mm; acc.w *= mm;

    const size_t m = (size_t)b * HWc + p;
    *(float4*)&g_col[m * KDIM + kk * 256 + c] = acc;
}

// ---------------------------------------------------------------------------
// Kernel 4: GEMM  out[b][n][p] = sum_k col[m][k] * wt[k][n],  m = b*4096+p
// 128x128 block tile, BK=16, 8x8 per thread, 256 threads.
// ---------------------------------------------------------------------------
__global__ __launch_bounds__(256) void k_gemm(float* __restrict__ out) {
    __shared__ float As[16][128];
    __shared__ float Bs[16][128];

    const int tid = threadIdx.x;
    const int bm = blockIdx.x * 128;
    const int bn = blockIdx.y * 128;
    const int tx = tid & 15;   // M micro-tile index
    const int ty = tid >> 4;   // N micro-tile index

    // global-load assignments
    const int a_row = tid >> 2;          // 0..63 (second group +64)
    const int a_k   = (tid & 3) * 4;     // 0,4,8,12
    const int b_k   = tid >> 5;          // 0..7 (second group +8)
    const int b_col = (tid & 31) * 4;    // 0..124

    float acc[8][8];
#pragma unroll
    for (int i = 0; i < 8; i++)
#pragma unroll
        for (int j = 0; j < 8; j++) acc[i][j] = 0.f;

    float4 pa0, pa1, pb0, pb1;

#define LOADG(KT)                                                              \
    {                                                                          \
        pa0 = *(const float4*)&g_col[(size_t)(bm + a_row) * KDIM + (KT) + a_k];        \
        pa1 = *(const float4*)&g_col[(size_t)(bm + a_row + 64) * KDIM + (KT) + a_k];   \
        pb0 = *(const float4*)&g_wt[(size_t)((KT) + b_k) * OO + bn + b_col];           \
        pb1 = *(const float4*)&g_wt[(size_t)((KT) + b_k + 8) * OO + bn + b_col];       \
    }
#define STORES()                                                               \
    {                                                                          \
        As[a_k + 0][a_row] = pa0.x; As[a_k + 1][a_row] = pa0.y;                \
        As[a_k + 2][a_row] = pa0.z; As[a_k + 3][a_row] = pa0.w;                \
        As[a_k + 0][a_row + 64] = pa1.x; As[a_k + 1][a_row + 64] = pa1.y;      \
        As[a_k + 2][a_row + 64] = pa1.z; As[a_k + 3][a_row + 64] = pa1.w;      \
        *(float4*)&Bs[b_k][b_col]     = pb0;                                   \
        *(float4*)&Bs[b_k + 8][b_col] = pb1;                                   \
    }

    LOADG(0);
    STORES();
    __syncthreads();

    for (int kt = 0; kt < KDIM; kt += 16) {
        const bool more = (kt + 16 < KDIM);
        if (more) LOADG(kt + 16);

        float ar[8], br[8];
#pragma unroll
        for (int kk = 0; kk < 16; kk++) {
            *(float4*)&ar[0] = *(const float4*)&As[kk][tx * 4];
            *(float4*)&ar[4] = *(const float4*)&As[kk][64 + tx * 4];
            *(float4*)&br[0] = *(const float4*)&Bs[kk][ty * 4];
            *(float4*)&br[4] = *(const float4*)&Bs[kk][64 + ty * 4];
#pragma unroll
            for (int i = 0; i < 8; i++)
#pragma unroll
                for (int j = 0; j < 8; j++)
                    acc[i][j] += ar[i] * br[j];
        }
        __syncthreads();
        if (more) {
            STORES();
            __syncthreads();
        }
    }
#undef LOADG
#undef STORES

    // write out: out[b][n][p], b = bm/4096, p0 = bm%4096
    const int b  = bm >> 12;
    const int p0 = bm & (HWc - 1);
#pragma unroll
    for (int j = 0; j < 8; j++) {
        const int n = bn + ((j < 4) ? (ty * 4 + j) : (64 + ty * 4 + j - 4));
        float* op = out + (size_t)(b * OO + n) * HWc + p0;
        const float4 v0 = make_float4(acc[0][j], acc[1][j], acc[2][j], acc[3][j]);
        const float4 v1 = make_float4(acc[4][j], acc[5][j], acc[6][j], acc[7][j]);
        *(float4*)(op + tx * 4)      = v0;
        *(float4*)(op + 64 + tx * 4) = v1;
    }
}

// ---------------------------------------------------------------------------
extern "C" void kernel_launch(void* const* d_in, const int* in_sizes, int n_in,
                              void* d_out, int out_size) {
    const float* x      = (const float*)d_in[0];  // (4,256,64,64)
    const float* offset = (const float*)d_in[1];  // (4,18,64,64)
    const float* mask   = (const float*)d_in[2];  // (4,9,64,64)
    const float* weight = (const float*)d_in[3];  // (256,256,3,3)
    float* out = (float*)d_out;                   // (4,256,64,64)

    // 1. x NCHW -> NHWC
    k_transpose<<<dim3(HWc / 32, CC / 32, BB), dim3(32, 8)>>>(x);

    // 2. weight reorder
    k_wt<<<(KDIM * OO) / 256, 256>>>(weight);

    // 3. bilinear im2col (4 sample points per 256-thread block)
    k_im2col<<<(BB * KKc * HWc) / 4, 256>>>(offset, mask);

    // 4. GEMM -> output
    k_gemm<<<dim3(MDIM / 128, OO / 128), 256>>>(out);
}

// round 4
// speedup vs baseline: 1.7429x; 1.7429x over previous
#include <cuda_runtime.h>
#include <cstdint>

// Problem constants
#define Hc   64
#define Wc   64
#define CC   256
#define BB   4
#define OO   256
#define KKc  9
#define HWc  4096
#define KDIM 2304            // C*KK
#define MDIM 16384           // B*H*W

// Scratch (static device allocations — allowed)
__device__ float g_xt[BB * HWc * CC];          // x in NHWC
__device__ float g_wt[OO * KDIM];              // weight [o][kk*256+c], tf32-rounded
__device__ float g_col[(size_t)MDIM * KDIM];   // im2col [M][KDIM], tf32-rounded

__device__ __forceinline__ float tf32r(float x) {
    uint32_t u;
    asm("cvt.rna.tf32.f32 %0, %1;" : "=r"(u) : "f"(x));
    return __uint_as_float(u);
}
__device__ __forceinline__ void cp16(void* dst, const void* src) {
    uint32_t d;
    asm("{ .reg .u64 t; cvta.to.shared.u64 t, %1; cvt.u32.u64 %0, t; }" : "=r"(d) : "l"(dst));
    asm volatile("cp.async.cg.shared.global [%0], [%1], 16;" :: "r"(d), "l"(src) : "memory");
}
#define CP_COMMIT() asm volatile("cp.async.commit_group;" ::: "memory")

__device__ __forceinline__ void mma_tf32(float* d, const uint32_t* a, const uint32_t* b) {
    asm volatile(
        "mma.sync.aligned.m16n8k8.row.col.f32.tf32.tf32.f32 "
        "{%0,%1,%2,%3}, {%4,%5,%6,%7}, {%8,%9}, {%0,%1,%2,%3};"
        : "+f"(d[0]), "+f"(d[1]), "+f"(d[2]), "+f"(d[3])
        : "r"(a[0]), "r"(a[1]), "r"(a[2]), "r"(a[3]), "r"(b[0]), "r"(b[1]));
}

// ---------------------------------------------------------------------------
// Kernel 1: NCHW -> NHWC transpose of x
// ---------------------------------------------------------------------------
__global__ void k_transpose(const float* __restrict__ x) {
    __shared__ float t[32][33];
    const int b  = blockIdx.z;
    const int p0 = blockIdx.x * 32;
    const int c0 = blockIdx.y * 32;
    const int tx = threadIdx.x, ty = threadIdx.y;
#pragma unroll
    for (int i = 0; i < 32; i += 8)
        t[ty + i][tx] = x[(size_t)(b * CC + c0 + ty + i) * HWc + p0 + tx];
    __syncthreads();
#pragma unroll
    for (int i = 0; i < 32; i += 8)
        g_xt[(size_t)(b * HWc + p0 + ty + i) * CC + c0 + tx] = t[tx][ty + i];
}

// ---------------------------------------------------------------------------
// Kernel 2: weight [O][C][KK] -> wt[o][kk*256+c] (N-major rows, K contiguous)
// ---------------------------------------------------------------------------
__global__ void k_wt(const float* __restrict__ w) {
    const int idx = blockIdx.x * 256 + threadIdx.x;   // over OO*KDIM
    const int o  = idx / KDIM;
    const int r  = idx - o * KDIM;
    const int kk = r >> 8;
    const int c  = r & 255;
    g_wt[idx] = tf32r(w[(o * CC + c) * KKc + kk]);
}

// ---------------------------------------------------------------------------
// Kernel 3: bilinear-sampled, masked im2col (tf32-rounded output)
// ---------------------------------------------------------------------------
__global__ void k_im2col(const float* __restrict__ off,
                         const float* __restrict__ msk) {
    const int t    = threadIdx.x;
    const int sp   = blockIdx.x * 4 + (t >> 6);
    const int lane = t & 63;

    const int p   = sp & (HWc - 1);
    const int tmp = sp >> 12;
    const int kk  = tmp % KKc;
    const int b   = tmp / KKc;
    const int ho  = p >> 6, wo = p & 63;
    const int ki  = kk / 3, kj = kk - ki * 3;

    const int obase = ((b * 2 * KKc + kk * 2) * Hc + ho) * Wc + wo;
    const float dy = off[obase];
    const float dx = off[obase + Hc * Wc];
    const float mm = msk[((b * KKc + kk) * Hc + ho) * Wc + wo];

    const float py = (float)(ho - 1 + ki) + dy;
    const float px = (float)(wo - 1 + kj) + dx;
    const float y0f = floorf(py), x0f = floorf(px);
    const int   y0 = (int)y0f,    x0 = (int)x0f;
    const float wy = py - y0f,    wx = px - x0f;

    const float w00 = (1.f - wy) * (1.f - wx);
    const float w01 = (1.f - wy) * wx;
    const float w10 = wy * (1.f - wx);
    const float w11 = wy * wx;

    const int c = lane * 4;
    float4 acc = make_float4(0.f, 0.f, 0.f, 0.f);
    const float* xb = g_xt + (size_t)b * HWc * CC;

#define GATHER(yy, xx, wgt)                                                    \
    if ((unsigned)(yy) < Hc && (unsigned)(xx) < Wc) {                          \
        const float4 v = *(const float4*)&xb[(size_t)((yy) * Wc + (xx)) * CC + c]; \
        acc.x += (wgt) * v.x; acc.y += (wgt) * v.y;                            \
        acc.z += (wgt) * v.z; acc.w += (wgt) * v.w;                            \
    }
    GATHER(y0,     x0,     w00)
    GATHER(y0,     x0 + 1, w01)
    GATHER(y0 + 1, x0,     w10)
    GATHER(y0 + 1, x0 + 1, w11)
#undef GATHER

    acc.x = tf32r(acc.x * mm); acc.y = tf32r(acc.y * mm);
    acc.z = tf32r(acc.z * mm); acc.w = tf32r(acc.w * mm);

    const size_t m = (size_t)b * HWc + p;
    *(float4*)&g_col[m * KDIM + kk * 256 + c] = acc;
}

// ---------------------------------------------------------------------------
// Kernel 4: tf32 mma.sync GEMM.  D[m][n] = sum_k col[m][k] * wt[n][k]
// CTA tile 128x128, BK=32, 3-stage cp.async. 8 warps, warp tile 64x32.
// smem A,B: [128 rows][36 floats] (pad -> conflict-free frag LDS)
// 256 threads: tid 0..127 load A rows, tid 128..255 load B rows.
// ---------------------------------------------------------------------------
#define NS     3
#define BKc    32
#define NCH    (KDIM / BKc)        // 72
#define ROWPAD 36
#define HALFST (128 * ROWPAD)      // floats per A (or B) stage = 4608
#define STAGEF (2 * HALFST)        // 9216 floats
#define GSMEM  (NS * STAGEF * 4)   // 110592 bytes

__device__ __forceinline__ void load_stage(float* sm, int s, int chunk,
                                           int bm, int bn, int tid) {
    const int r = tid & 127;
    float* dst;
    const float* src;
    if (tid < 128) {
        dst = sm + s * STAGEF + r * ROWPAD;
        src = g_col + (size_t)(bm + r) * KDIM + chunk * BKc;
    } else {
        dst = sm + s * STAGEF + HALFST + r * ROWPAD;
        src = g_wt + (size_t)(bn + r) * KDIM + chunk * BKc;
    }
#pragma unroll
    for (int j = 0; j < 8; j++) cp16(dst + j * 4, src + j * 4);
}

__global__ __launch_bounds__(256) void k_gemm_mma(float* __restrict__ out) {
    extern __shared__ float sm[];

    const int tid  = threadIdx.x;
    const int wid  = tid >> 5;
    const int lane = tid & 31;
    const int g    = lane >> 2;      // 0..7
    const int tig  = lane & 3;       // 0..3
    const int wm   = wid & 1;        // M block (64)
    const int wn   = wid >> 1;       // N block (32)
    const int bn   = blockIdx.x * 128;
    const int bm   = blockIdx.y * 128;

    float acc[4][4][4];
#pragma unroll
    for (int i = 0; i < 4; i++)
#pragma unroll
        for (int j = 0; j < 4; j++)
#pragma unroll
            for (int r = 0; r < 4; r++) acc[i][j][r] = 0.f;

    // prologue: stages 0,1
    load_stage(sm, 0, 0, bm, bn, tid); CP_COMMIT();
    load_stage(sm, 1, 1, bm, bn, tid); CP_COMMIT();

    for (int i = 0; i < NCH; i++) {
        const int s = i % NS;
        if (i + 2 < NCH) { load_stage(sm, (i + 2) % NS, i + 2, bm, bn, tid); CP_COMMIT(); }

        if (i + 2 < NCH)      asm volatile("cp.async.wait_group 2;" ::: "memory");
        else if (i + 1 < NCH) asm volatile("cp.async.wait_group 1;" ::: "memory");
        else                  asm volatile("cp.async.wait_group 0;" ::: "memory");
        __syncthreads();

        const uint32_t* A = (const uint32_t*)(sm + s * STAGEF);
        const uint32_t* B = A + HALFST;
        const uint32_t* Ab = A + (wm * 64 + g) * ROWPAD + tig;
        const uint32_t* Bb = B + (wn * 32 + g) * ROWPAD + tig;

#pragma unroll
        for (int ks = 0; ks < 4; ks++) {
            uint32_t af[4][4], bf[4][2];
            const int ko = ks * 8;
#pragma unroll
            for (int ii = 0; ii < 4; ii++) {
                const uint32_t* p = Ab + ii * 16 * ROWPAD + ko;
                af[ii][0] = p[0];
                af[ii][1] = p[8 * ROWPAD];
                af[ii][2] = p[4];
                af[ii][3] = p[8 * ROWPAD + 4];
            }
#pragma unroll
            for (int jj = 0; jj < 4; jj++) {
                const uint32_t* p = Bb + jj * 8 * ROWPAD + ko;
                bf[jj][0] = p[0];
                bf[jj][1] = p[4];
            }
#pragma unroll
            for (int ii = 0; ii < 4; ii++)
#pragma unroll
                for (int jj = 0; jj < 4; jj++)
                    mma_tf32(acc[ii][jj], af[ii], bf[jj]);
        }
        __syncthreads();
    }

    // epilogue: out[b][n][p];  m = wm*64 + ii*16 + g (+8), n = wn*32 + jj*8 + tig*2 (+1)
    const int b  = bm >> 12;
    const int p0 = (bm & (HWc - 1)) + wm * 64 + g;
    float* ob = out + ((size_t)b * OO << 12) + p0;
#pragma unroll
    for (int jj = 0; jj < 4; jj++) {
        const int n = bn + wn * 32 + jj * 8 + tig * 2;
        float* o0 = ob + ((size_t)n << 12);
        float* o1 = o0 + HWc;
#pragma unroll
        for (int ii = 0; ii < 4; ii++) {
            const int mo = ii * 16;
            o0[mo]     = acc[ii][jj][0];
            o1[mo]     = acc[ii][jj][1];
            o0[mo + 8] = acc[ii][jj][2];
            o1[mo + 8] = acc[ii][jj][3];
        }
    }
}

// ---------------------------------------------------------------------------
extern "C" void kernel_launch(void* const* d_in, const int* in_sizes, int n_in,
                              void* d_out, int out_size) {
    const float* x      = (const float*)d_in[0];
    const float* offset = (const float*)d_in[1];
    const float* mask   = (const float*)d_in[2];
    const float* weight = (const float*)d_in[3];
    float* out = (float*)d_out;

    cudaFuncSetAttribute(k_gemm_mma, cudaFuncAttributeMaxDynamicSharedMemorySize, GSMEM);

    k_transpose<<<dim3(HWc / 32, CC / 32, BB), dim3(32, 8)>>>(x);
    k_wt<<<(OO * KDIM) / 256, 256>>>(weight);
    k_im2col<<<(BB * KKc * HWc) / 4, 256>>>(offset, mask);
    k_gemm_mma<<<dim3(OO / 128, MDIM / 128), 256, GSMEM>>>(out);
}

// round 5
// speedup vs baseline: 1.7794x; 1.0209x over previous
#include <cuda_runtime.h>
#include <cstdint>

// Problem constants
#define Hc   64
#define Wc   64
#define CC   256
#define BB   4
#define OO   256
#define KKc  9
#define HWc  4096
#define KDIM 2304            // C*KK
#define MDIM 16384           // B*H*W

// Scratch (static device allocations — allowed)
__device__ float g_xt[BB * HWc * CC];          // x in NHWC
__device__ float g_wt[OO * KDIM];              // weight [o][kk*256+c], tf32-rounded
__device__ float g_col[(size_t)MDIM * KDIM];   // im2col [M][KDIM], tf32-rounded

__device__ __forceinline__ float tf32r(float x) {
    uint32_t u;
    asm("cvt.rna.tf32.f32 %0, %1;" : "=r"(u) : "f"(x));
    return __uint_as_float(u);
}
__device__ __forceinline__ void cp16(void* dst, const void* src) {
    uint32_t d;
    asm("{ .reg .u64 t; cvta.to.shared.u64 t, %1; cvt.u32.u64 %0, t; }" : "=r"(d) : "l"(dst));
    asm volatile("cp.async.cg.shared.global [%0], [%1], 16;" :: "r"(d), "l"(src) : "memory");
}
#define CP_COMMIT() asm volatile("cp.async.commit_group;" ::: "memory")

__device__ __forceinline__ void mma_tf32(float* d, const uint32_t* a, const uint32_t* b) {
    asm volatile(
        "mma.sync.aligned.m16n8k8.row.col.f32.tf32.tf32.f32 "
        "{%0,%1,%2,%3}, {%4,%5,%6,%7}, {%8,%9}, {%0,%1,%2,%3};"
        : "+f"(d[0]), "+f"(d[1]), "+f"(d[2]), "+f"(d[3])
        : "r"(a[0]), "r"(a[1]), "r"(a[2]), "r"(a[3]), "r"(b[0]), "r"(b[1]));
}

// ---------------------------------------------------------------------------
// Kernel 1: NCHW -> NHWC transpose of x
// ---------------------------------------------------------------------------
__global__ void k_transpose(const float* __restrict__ x) {
    __shared__ float t[32][33];
    const int b  = blockIdx.z;
    const int p0 = blockIdx.x * 32;
    const int c0 = blockIdx.y * 32;
    const int tx = threadIdx.x, ty = threadIdx.y;
#pragma unroll
    for (int i = 0; i < 32; i += 8)
        t[ty + i][tx] = x[(size_t)(b * CC + c0 + ty + i) * HWc + p0 + tx];
    __syncthreads();
#pragma unroll
    for (int i = 0; i < 32; i += 8)
        g_xt[(size_t)(b * HWc + p0 + ty + i) * CC + c0 + tx] = t[tx][ty + i];
}

// ---------------------------------------------------------------------------
// Kernel 2: weight [O][C][KK] -> wt[o][kk*256+c]
// ---------------------------------------------------------------------------
__global__ void k_wt(const float* __restrict__ w) {
    const int idx = blockIdx.x * 256 + threadIdx.x;   // over OO*KDIM
    const int o  = idx / KDIM;
    const int r  = idx - o * KDIM;
    const int kk = r >> 8;
    const int c  = r & 255;
    g_wt[idx] = tf32r(w[(o * CC + c) * KKc + kk]);
}

// ---------------------------------------------------------------------------
// Kernel 3: bilinear-sampled, masked im2col (tf32-rounded output)
// ---------------------------------------------------------------------------
__global__ void k_im2col(const float* __restrict__ off,
                         const float* __restrict__ msk) {
    const int t    = threadIdx.x;
    const int sp   = blockIdx.x * 4 + (t >> 6);
    const int lane = t & 63;

    const int p   = sp & (HWc - 1);
    const int tmp = sp >> 12;
    const int kk  = tmp % KKc;
    const int b   = tmp / KKc;
    const int ho  = p >> 6, wo = p & 63;
    const int ki  = kk / 3, kj = kk - ki * 3;

    const int obase = ((b * 2 * KKc + kk * 2) * Hc + ho) * Wc + wo;
    const float dy = off[obase];
    const float dx = off[obase + Hc * Wc];
    const float mm = msk[((b * KKc + kk) * Hc + ho) * Wc + wo];

    const float py = (float)(ho - 1 + ki) + dy;
    const float px = (float)(wo - 1 + kj) + dx;
    const float y0f = floorf(py), x0f = floorf(px);
    const int   y0 = (int)y0f,    x0 = (int)x0f;
    const float wy = py - y0f,    wx = px - x0f;

    const float w00 = (1.f - wy) * (1.f - wx);
    const float w01 = (1.f - wy) * wx;
    const float w10 = wy * (1.f - wx);
    const float w11 = wy * wx;

    const int c = lane * 4;
    float4 acc = make_float4(0.f, 0.f, 0.f, 0.f);
    const float* xb = g_xt + (size_t)b * HWc * CC;

#define GATHER(yy, xx, wgt)                                                    \
    if ((unsigned)(yy) < Hc && (unsigned)(xx) < Wc) {                          \
        const float4 v = *(const float4*)&xb[(size_t)((yy) * Wc + (xx)) * CC + c]; \
        acc.x += (wgt) * v.x; acc.y += (wgt) * v.y;                            \
        acc.z += (wgt) * v.z; acc.w += (wgt) * v.w;                            \
    }
    GATHER(y0,     x0,     w00)
    GATHER(y0,     x0 + 1, w01)
    GATHER(y0 + 1, x0,     w10)
    GATHER(y0 + 1, x0 + 1, w11)
#undef GATHER

    acc.x = tf32r(acc.x * mm); acc.y = tf32r(acc.y * mm);
    acc.z = tf32r(acc.z * mm); acc.w = tf32r(acc.w * mm);

    const size_t m = (size_t)b * HWc + p;
    *(float4*)&g_col[m * KDIM + kk * 256 + c] = acc;
}

// ---------------------------------------------------------------------------
// Kernel 4: tf32 mma.sync GEMM.  D[m][n] = sum_k col[m][k] * wt[n][k]
// CTA tile 128x128, BK=32, 3-stage cp.async, ONE __syncthreads per chunk,
// 2 CTAs/SM resident (216KB smem total). 8 warps, warp tile 64x32.
// ---------------------------------------------------------------------------
#define NS     3
#define BKc    32
#define NCH    (KDIM / BKc)        // 72
#define ROWPAD 36
#define HALFST (128 * ROWPAD)      // floats per A (or B) stage = 4608
#define STAGEF (2 * HALFST)        // 9216 floats
#define GSMEM  (NS * STAGEF * 4)   // 110592 bytes

__device__ __forceinline__ void load_stage(float* sm, int s, int chunk,
                                           int bm, int bn, int tid) {
    const int r = tid & 127;
    float* dst;
    const float* src;
    if (tid < 128) {
        dst = sm + s * STAGEF + r * ROWPAD;
        src = g_col + (size_t)(bm + r) * KDIM + chunk * BKc;
    } else {
        dst = sm + s * STAGEF + HALFST + r * ROWPAD;
        src = g_wt + (size_t)(bn + r) * KDIM + chunk * BKc;
    }
#pragma unroll
    for (int j = 0; j < 8; j++) cp16(dst + j * 4, src + j * 4);
}

__global__ __launch_bounds__(256, 2) void k_gemm_mma(float* __restrict__ out) {
    extern __shared__ float sm[];

    const int tid  = threadIdx.x;
    const int wid  = tid >> 5;
    const int lane = tid & 31;
    const int g    = lane >> 2;      // 0..7
    const int tig  = lane & 3;       // 0..3
    const int wm   = wid & 1;        // M block (64)
    const int wn   = wid >> 1;       // N block (32)
    const int bn   = blockIdx.x * 128;
    const int bm   = blockIdx.y * 128;

    float acc[4][4][4];
#pragma unroll
    for (int i = 0; i < 4; i++)
#pragma unroll
        for (int j = 0; j < 4; j++)
#pragma unroll
            for (int r = 0; r < 4; r++) acc[i][j][r] = 0.f;

    // prologue: stages 0,1
    load_stage(sm, 0, 0, bm, bn, tid); CP_COMMIT();
    load_stage(sm, 1, 1, bm, bn, tid); CP_COMMIT();

    for (int i = 0; i < NCH; i++) {
        const int s = i % NS;

        // stage i is complete when at most 1 group (load i+1) remains pending
        asm volatile("cp.async.wait_group 1;" ::: "memory");
        __syncthreads();   // also guarantees compute of chunk i-1 finished
                           // -> stage (i+2)%NS is free for reuse

        if (i + 2 < NCH) load_stage(sm, (i + 2) % NS, i + 2, bm, bn, tid);
        CP_COMMIT();       // commit (possibly empty) group to keep accounting

        const uint32_t* A = (const uint32_t*)(sm + s * STAGEF);
        const uint32_t* B = A + HALFST;
        const uint32_t* Ab = A + (wm * 64 + g) * ROWPAD + tig;
        const uint32_t* Bb = B + (wn * 32 + g) * ROWPAD + tig;

#pragma unroll
        for (int ks = 0; ks < 4; ks++) {
            uint32_t af[4][4], bf[4][2];
            const int ko = ks * 8;
#pragma unroll
            for (int ii = 0; ii < 4; ii++) {
                const uint32_t* p = Ab + ii * 16 * ROWPAD + ko;
                af[ii][0] = p[0];
                af[ii][1] = p[8 * ROWPAD];
                af[ii][2] = p[4];
                af[ii][3] = p[8 * ROWPAD + 4];
            }
#pragma unroll
            for (int jj = 0; jj < 4; jj++) {
                const uint32_t* p = Bb + jj * 8 * ROWPAD + ko;
                bf[jj][0] = p[0];
                bf[jj][1] = p[4];
            }
#pragma unroll
            for (int ii = 0; ii < 4; ii++)
#pragma unroll
                for (int jj = 0; jj < 4; jj++)
                    mma_tf32(acc[ii][jj], af[ii], bf[jj]);
        }
    }

    // epilogue: out[b][n][p];  m = wm*64 + ii*16 + g (+8), n = wn*32 + jj*8 + tig*2 (+1)
    const int b  = bm >> 12;
    const int p0 = (bm & (HWc - 1)) + wm * 64 + g;
    float* ob = out + ((size_t)b * OO << 12) + p0;
#pragma unroll
    for (int jj = 0; jj < 4; jj++) {
        const int n = bn + wn * 32 + jj * 8 + tig * 2;
        float* o0 = ob + ((size_t)n << 12);
        float* o1 = o0 + HWc;
#pragma unroll
        for (int ii = 0; ii < 4; ii++) {
            const int mo = ii * 16;
            o0[mo]     = acc[ii][jj][0];
            o1[mo]     = acc[ii][jj][1];
            o0[mo + 8] = acc[ii][jj][2];
            o1[mo + 8] = acc[ii][jj][3];
        }
    }
}

// ---------------------------------------------------------------------------
extern "C" void kernel_launch(void* const* d_in, const int* in_sizes, int n_in,
                              void* d_out, int out_size) {
    const float* x      = (const float*)d_in[0];
    const float* offset = (const float*)d_in[1];
    const float* mask   = (const float*)d_in[2];
    const float* weight = (const float*)d_in[3];
    float* out = (float*)d_out;

    cudaFuncSetAttribute(k_gemm_mma, cudaFuncAttributeMaxDynamicSharedMemorySize, GSMEM);

    k_transpose<<<dim3(HWc / 32, CC / 32, BB), dim3(32, 8)>>>(x);
    k_wt<<<(OO * KDIM) / 256, 256>>>(weight);
    k_im2col<<<(BB * KKc * HWc) / 4, 256>>>(offset, mask);
    k_gemm_mma<<<dim3(OO / 128, MDIM / 128), 256, GSMEM>>>(out);
}

// round 6
// speedup vs baseline: 1.8096x; 1.0170x over previous
#include <cuda_runtime.h>
#include <cstdint>

// Problem constants
#define Hc   64
#define Wc   64
#define CC   256
#define BB   4
#define OO   256
#define KKc  9
#define HWc  4096
#define KDIM 2304            // C*KK
#define MDIM 16384           // B*H*W

// Scratch (static device allocations — allowed)
__device__ float g_xt[BB * HWc * CC];          // x in NHWC
__device__ float g_wt[OO * KDIM];              // weight [o][kk*256+c], tf32-rounded
__device__ float g_col[(size_t)MDIM * KDIM];   // im2col [M][KDIM], tf32-rounded

__device__ __forceinline__ float tf32r(float x) {
    uint32_t u;
    asm("cvt.rna.tf32.f32 %0, %1;" : "=r"(u) : "f"(x));
    return __uint_as_float(u);
}
__device__ __forceinline__ void cp16(void* dst, const void* src) {
    uint32_t d;
    asm("{ .reg .u64 t; cvta.to.shared.u64 t, %1; cvt.u32.u64 %0, t; }" : "=r"(d) : "l"(dst));
    asm volatile("cp.async.cg.shared.global [%0], [%1], 16;" :: "r"(d), "l"(src) : "memory");
}
#define CP_COMMIT() asm volatile("cp.async.commit_group;" ::: "memory")

__device__ __forceinline__ void mma_tf32(float* d, const uint32_t* a, const uint32_t* b) {
    asm volatile(
        "mma.sync.aligned.m16n8k8.row.col.f32.tf32.tf32.f32 "
        "{%0,%1,%2,%3}, {%4,%5,%6,%7}, {%8,%9}, {%0,%1,%2,%3};"
        : "+f"(d[0]), "+f"(d[1]), "+f"(d[2]), "+f"(d[3])
        : "r"(a[0]), "r"(a[1]), "r"(a[2]), "r"(a[3]), "r"(b[0]), "r"(b[1]));
}

// ---------------------------------------------------------------------------
// Kernel 1: NCHW -> NHWC transpose of x
// ---------------------------------------------------------------------------
__global__ void k_transpose(const float* __restrict__ x) {
    __shared__ float t[32][33];
    const int b  = blockIdx.z;
    const int p0 = blockIdx.x * 32;
    const int c0 = blockIdx.y * 32;
    const int tx = threadIdx.x, ty = threadIdx.y;
#pragma unroll
    for (int i = 0; i < 32; i += 8)
        t[ty + i][tx] = x[(size_t)(b * CC + c0 + ty + i) * HWc + p0 + tx];
    __syncthreads();
#pragma unroll
    for (int i = 0; i < 32; i += 8)
        g_xt[(size_t)(b * HWc + p0 + ty + i) * CC + c0 + tx] = t[tx][ty + i];
}

// ---------------------------------------------------------------------------
// Kernel 2: weight [O][C][KK] -> wt[o][kk*256+c]
// ---------------------------------------------------------------------------
__global__ void k_wt(const float* __restrict__ w) {
    const int idx = blockIdx.x * 256 + threadIdx.x;   // over OO*KDIM
    const int o  = idx / KDIM;
    const int r  = idx - o * KDIM;
    const int kk = r >> 8;
    const int c  = r & 255;
    g_wt[idx] = tf32r(w[(o * CC + c) * KKc + kk]);
}

// ---------------------------------------------------------------------------
// Kernel 3: bilinear-sampled, masked im2col (tf32-rounded output)
// ---------------------------------------------------------------------------
__global__ void k_im2col(const float* __restrict__ off,
                         const float* __restrict__ msk) {
    const int t    = threadIdx.x;
    const int sp   = blockIdx.x * 4 + (t >> 6);
    const int lane = t & 63;

    const int p   = sp & (HWc - 1);
    const int tmp = sp >> 12;
    const int kk  = tmp % KKc;
    const int b   = tmp / KKc;
    const int ho  = p >> 6, wo = p & 63;
    const int ki  = kk / 3, kj = kk - ki * 3;

    const int obase = ((b * 2 * KKc + kk * 2) * Hc + ho) * Wc + wo;
    const float dy = off[obase];
    const float dx = off[obase + Hc * Wc];
    const float mm = msk[((b * KKc + kk) * Hc + ho) * Wc + wo];

    const float py = (float)(ho - 1 + ki) + dy;
    const float px = (float)(wo - 1 + kj) + dx;
    const float y0f = floorf(py), x0f = floorf(px);
    const int   y0 = (int)y0f,    x0 = (int)x0f;
    const float wy = py - y0f,    wx = px - x0f;

    const float w00 = (1.f - wy) * (1.f - wx);
    const float w01 = (1.f - wy) * wx;
    const float w10 = wy * (1.f - wx);
    const float w11 = wy * wx;

    const int c = lane * 4;
    float4 acc = make_float4(0.f, 0.f, 0.f, 0.f);
    const float* xb = g_xt + (size_t)b * HWc * CC;

#define GATHER(yy, xx, wgt)                                                    \
    if ((unsigned)(yy) < Hc && (unsigned)(xx) < Wc) {                          \
        const float4 v = *(const float4*)&xb[(size_t)((yy) * Wc + (xx)) * CC + c]; \
        acc.x += (wgt) * v.x; acc.y += (wgt) * v.y;                            \
        acc.z += (wgt) * v.z; acc.w += (wgt) * v.w;                            \
    }
    GATHER(y0,     x0,     w00)
    GATHER(y0,     x0 + 1, w01)
    GATHER(y0 + 1, x0,     w10)
    GATHER(y0 + 1, x0 + 1, w11)
#undef GATHER

    acc.x = tf32r(acc.x * mm); acc.y = tf32r(acc.y * mm);
    acc.z = tf32r(acc.z * mm); acc.w = tf32r(acc.w * mm);

    const size_t m = (size_t)b * HWc + p;
    *(float4*)&g_col[m * KDIM + kk * 256 + c] = acc;
}

// ---------------------------------------------------------------------------
// Kernel 4: tf32 mma.sync GEMM.  D[m][n] = sum_k col[m][k] * wt[n][k]
// CTA tile 128x128, 4 warps (128 thr), warp tile 64x64 (2x2 warp grid),
// BK=32, NS=3 cp.async stages, one barrier per chunk, 2 CTAs/SM.
// ---------------------------------------------------------------------------
#define NS     3
#define BKc    32
#define NCH    (KDIM / BKc)        // 72
#define ROWPAD 36
#define HALFST (128 * ROWPAD)      // floats per A (or B) stage = 4608
#define STAGEF (2 * HALFST)        // 9216 floats
#define GSMEM  (NS * STAGEF * 4)   // 110592 bytes

__device__ __forceinline__ void load_stage(float* sm, int s, int chunk,
                                           int bm, int bn, int tid) {
    // 128 threads: each loads one A row and one B row (8 cp16 each)
    float* Ad = sm + s * STAGEF + tid * ROWPAD;
    float* Bd = Ad + HALFST;
    const float* asrc = g_col + (size_t)(bm + tid) * KDIM + chunk * BKc;
    const float* bsrc = g_wt  + (size_t)(bn + tid) * KDIM + chunk * BKc;
#pragma unroll
    for (int j = 0; j < 8; j++) cp16(Ad + j * 4, asrc + j * 4);
#pragma unroll
    for (int j = 0; j < 8; j++) cp16(Bd + j * 4, bsrc + j * 4);
}

__global__ __launch_bounds__(128, 2) void k_gemm_mma(float* __restrict__ out) {
    extern __shared__ float sm[];

    const int tid  = threadIdx.x;
    const int wid  = tid >> 5;
    const int lane = tid & 31;
    const int g    = lane >> 2;      // 0..7
    const int tig  = lane & 3;       // 0..3
    const int wm   = wid & 1;        // M half (64)
    const int wn   = wid >> 1;       // N half (64)
    const int bn   = blockIdx.x * 128;
    const int bm   = blockIdx.y * 128;

    float acc[4][8][4];
#pragma unroll
    for (int i = 0; i < 4; i++)
#pragma unroll
        for (int j = 0; j < 8; j++)
#pragma unroll
            for (int r = 0; r < 4; r++) acc[i][j][r] = 0.f;

    // prologue: stages 0,1
    load_stage(sm, 0, 0, bm, bn, tid); CP_COMMIT();
    load_stage(sm, 1, 1, bm, bn, tid); CP_COMMIT();

    for (int i = 0; i < NCH; i++) {
        const int s = i % NS;

        asm volatile("cp.async.wait_group 1;" ::: "memory");
        __syncthreads();   // stage i ready; stage (i+2)%NS free (chunk i-1 done)

        if (i + 2 < NCH) load_stage(sm, (i + 2) % NS, i + 2, bm, bn, tid);
        CP_COMMIT();

        const uint32_t* A = (const uint32_t*)(sm + s * STAGEF);
        const uint32_t* B = A + HALFST;
        const uint32_t* Ab = A + (wm * 64 + g) * ROWPAD + tig;
        const uint32_t* Bb = B + (wn * 64 + g) * ROWPAD + tig;

#pragma unroll
        for (int ks = 0; ks < 4; ks++) {
            uint32_t af[4][4], bf[8][2];
            const int ko = ks * 8;
#pragma unroll
            for (int ii = 0; ii < 4; ii++) {
                const uint32_t* p = Ab + ii * 16 * ROWPAD + ko;
                af[ii][0] = p[0];
                af[ii][1] = p[8 * ROWPAD];
                af[ii][2] = p[4];
                af[ii][3] = p[8 * ROWPAD + 4];
            }
#pragma unroll
            for (int jj = 0; jj < 8; jj++) {
                const uint32_t* p = Bb + jj * 8 * ROWPAD + ko;
                bf[jj][0] = p[0];
                bf[jj][1] = p[4];
            }
#pragma unroll
            for (int ii = 0; ii < 4; ii++)
#pragma unroll
                for (int jj = 0; jj < 8; jj++)
                    mma_tf32(acc[ii][jj], af[ii], bf[jj]);
        }
    }

    // epilogue: out[b][n][p];  m = wm*64 + ii*16 + g (+8), n = wn*64 + jj*8 + tig*2 (+1)
    const int b  = bm >> 12;
    const int p0 = (bm & (HWc - 1)) + wm * 64 + g;
    float* ob = out + ((size_t)b * OO << 12) + p0;
#pragma unroll
    for (int jj = 0; jj < 8; jj++) {
        const int n = bn + wn * 64 + jj * 8 + tig * 2;
        float* o0 = ob + ((size_t)n << 12);
        float* o1 = o0 + HWc;
#pragma unroll
        for (int ii = 0; ii < 4; ii++) {
            const int mo = ii * 16;
            o0[mo]     = acc[ii][jj][0];
            o1[mo]     = acc[ii][jj][1];
            o0[mo + 8] = acc[ii][jj][2];
            o1[mo + 8] = acc[ii][jj][3];
        }
    }
}

// ---------------------------------------------------------------------------
extern "C" void kernel_launch(void* const* d_in, const int* in_sizes, int n_in,
                              void* d_out, int out_size) {
    const float* x      = (const float*)d_in[0];
    const float* offset = (const float*)d_in[1];
    const float* mask   = (const float*)d_in[2];
    const float* weight = (const float*)d_in[3];
    float* out = (float*)d_out;

    cudaFuncSetAttribute(k_gemm_mma, cudaFuncAttributeMaxDynamicSharedMemorySize, GSMEM);

    k_transpose<<<dim3(HWc / 32, CC / 32, BB), dim3(32, 8)>>>(x);
    k_wt<<<(OO * KDIM) / 256, 256>>>(weight);
    k_im2col<<<(BB * KKc * HWc) / 4, 256>>>(offset, mask);
    k_gemm_mma<<<dim3(OO / 128, MDIM / 128), 128, GSMEM>>>(out);
}

// round 7
// speedup vs baseline: 1.8141x; 1.0025x over previous
#include <cuda_runtime.h>
#include <cstdint>

// Problem constants
#define Hc   64
#define Wc   64
#define CC   256
#define BB   4
#define OO   256
#define KKc  9
#define HWc  4096
#define KDIM 2304            // C*KK
#define MDIM 16384           // B*H*W

// Scratch (static device allocations — allowed)
__device__ float g_xt[BB * HWc * CC];          // x in NHWC
__device__ float g_wt[OO * KDIM];              // weight [o][kk*256+c], tf32-rounded
__device__ float g_col[(size_t)MDIM * KDIM];   // im2col [M][KDIM], tf32-rounded

__device__ __forceinline__ float tf32r(float x) {
    uint32_t u;
    asm("cvt.rna.tf32.f32 %0, %1;" : "=r"(u) : "f"(x));
    return __uint_as_float(u);
}
__device__ __forceinline__ void cp16(void* dst, const void* src) {
    uint32_t d;
    asm("{ .reg .u64 t; cvta.to.shared.u64 t, %1; cvt.u32.u64 %0, t; }" : "=r"(d) : "l"(dst));
    asm volatile("cp.async.cg.shared.global [%0], [%1], 16;" :: "r"(d), "l"(src) : "memory");
}
#define CP_COMMIT() asm volatile("cp.async.commit_group;" ::: "memory")

__device__ __forceinline__ void mma_tf32(float* d, const uint32_t* a, const uint32_t* b) {
    asm volatile(
        "mma.sync.aligned.m16n8k8.row.col.f32.tf32.tf32.f32 "
        "{%0,%1,%2,%3}, {%4,%5,%6,%7}, {%8,%9}, {%0,%1,%2,%3};"
        : "+f"(d[0]), "+f"(d[1]), "+f"(d[2]), "+f"(d[3])
        : "r"(a[0]), "r"(a[1]), "r"(a[2]), "r"(a[3]), "r"(b[0]), "r"(b[1]));
}

// ---------------------------------------------------------------------------
// Kernel 1: NCHW -> NHWC transpose of x
// ---------------------------------------------------------------------------
__global__ void k_transpose(const float* __restrict__ x) {
    __shared__ float t[32][33];
    const int b  = blockIdx.z;
    const int p0 = blockIdx.x * 32;
    const int c0 = blockIdx.y * 32;
    const int tx = threadIdx.x, ty = threadIdx.y;
#pragma unroll
    for (int i = 0; i < 32; i += 8)
        t[ty + i][tx] = x[(size_t)(b * CC + c0 + ty + i) * HWc + p0 + tx];
    __syncthreads();
#pragma unroll
    for (int i = 0; i < 32; i += 8)
        g_xt[(size_t)(b * HWc + p0 + ty + i) * CC + c0 + tx] = t[tx][ty + i];
}

// ---------------------------------------------------------------------------
// Kernel 2: weight [O][C][KK] -> wt[o][kk*256+c]
// ---------------------------------------------------------------------------
__global__ void k_wt(const float* __restrict__ w) {
    const int idx = blockIdx.x * 256 + threadIdx.x;   // over OO*KDIM
    const int o  = idx / KDIM;
    const int r  = idx - o * KDIM;
    const int kk = r >> 8;
    const int c  = r & 255;
    g_wt[idx] = tf32r(w[(o * CC + c) * KKc + kk]);
}

// ---------------------------------------------------------------------------
// Kernel 3: bilinear-sampled, masked im2col (tf32-rounded output)
// ---------------------------------------------------------------------------
__global__ void k_im2col(const float* __restrict__ off,
                         const float* __restrict__ msk) {
    const int t    = threadIdx.x;
    const int sp   = blockIdx.x * 4 + (t >> 6);
    const int lane = t & 63;

    const int p   = sp & (HWc - 1);
    const int tmp = sp >> 12;
    const int kk  = tmp % KKc;
    const int b   = tmp / KKc;
    const int ho  = p >> 6, wo = p & 63;
    const int ki  = kk / 3, kj = kk - ki * 3;

    const int obase = ((b * 2 * KKc + kk * 2) * Hc + ho) * Wc + wo;
    const float dy = off[obase];
    const float dx = off[obase + Hc * Wc];
    const float mm = msk[((b * KKc + kk) * Hc + ho) * Wc + wo];

    const float py = (float)(ho - 1 + ki) + dy;
    const float px = (float)(wo - 1 + kj) + dx;
    const float y0f = floorf(py), x0f = floorf(px);
    const int   y0 = (int)y0f,    x0 = (int)x0f;
    const float wy = py - y0f,    wx = px - x0f;

    const float w00 = (1.f - wy) * (1.f - wx);
    const float w01 = (1.f - wy) * wx;
    const float w10 = wy * (1.f - wx);
    const float w11 = wy * wx;

    const int c = lane * 4;
    float4 acc = make_float4(0.f, 0.f, 0.f, 0.f);
    const float* xb = g_xt + (size_t)b * HWc * CC;

#define GATHER(yy, xx, wgt)                                                    \
    if ((unsigned)(yy) < Hc && (unsigned)(xx) < Wc) {                          \
        const float4 v = *(const float4*)&xb[(size_t)((yy) * Wc + (xx)) * CC + c]; \
        acc.x += (wgt) * v.x; acc.y += (wgt) * v.y;                            \
        acc.z += (wgt) * v.z; acc.w += (wgt) * v.w;                            \
    }
    GATHER(y0,     x0,     w00)
    GATHER(y0,     x0 + 1, w01)
    GATHER(y0 + 1, x0,     w10)
    GATHER(y0 + 1, x0 + 1, w11)
#undef GATHER

    acc.x = tf32r(acc.x * mm); acc.y = tf32r(acc.y * mm);
    acc.z = tf32r(acc.z * mm); acc.w = tf32r(acc.w * mm);

    const size_t m = (size_t)b * HWc + p;
    *(float4*)&g_col[m * KDIM + kk * 256 + c] = acc;
}

// ---------------------------------------------------------------------------
// Kernel 4: tf32 mma.sync GEMM.  D[m][n] = sum_k col[m][k] * wt[n][k]
// CTA tile 128x128, 4 warps (128 thr), warp tile 64x64 (2x2 warp grid),
// BK=32, NS=3 cp.async stages, one barrier per chunk, 2 CTAs/SM.
// ---------------------------------------------------------------------------
#define NS     3
#define BKc    32
#define NCH    (KDIM / BKc)        // 72
#define ROWPAD 36
#define HALFST (128 * ROWPAD)      // floats per A (or B) stage = 4608
#define STAGEF (2 * HALFST)        // 9216 floats
#define GSMEM  (NS * STAGEF * 4)   // 110592 bytes

__device__ __forceinline__ void load_stage(float* sm, int s, int chunk,
                                           int bm, int bn, int tid) {
    // 128 threads: each loads one A row and one B row (8 cp16 each)
    float* Ad = sm + s * STAGEF + tid * ROWPAD;
    float* Bd = Ad + HALFST;
    const float* asrc = g_col + (size_t)(bm + tid) * KDIM + chunk * BKc;
    const float* bsrc = g_wt  + (size_t)(bn + tid) * KDIM + chunk * BKc;
#pragma unroll
    for (int j = 0; j < 8; j++) cp16(Ad + j * 4, asrc + j * 4);
#pragma unroll
    for (int j = 0; j < 8; j++) cp16(Bd + j * 4, bsrc + j * 4);
}

__global__ __launch_bounds__(128, 2) void k_gemm_mma(float* __restrict__ out) {
    extern __shared__ float sm[];

    const int tid  = threadIdx.x;
    const int wid  = tid >> 5;
    const int lane = tid & 31;
    const int g    = lane >> 2;      // 0..7
    const int tig  = lane & 3;       // 0..3
    const int wm   = wid & 1;        // M half (64)
    const int wn   = wid >> 1;       // N half (64)
    const int bn   = blockIdx.x * 128;
    const int bm   = blockIdx.y * 128;

    float acc[4][8][4];
#pragma unroll
    for (int i = 0; i < 4; i++)
#pragma unroll
        for (int j = 0; j < 8; j++)
#pragma unroll
            for (int r = 0; r < 4; r++) acc[i][j][r] = 0.f;

    // prologue: stages 0,1
    load_stage(sm, 0, 0, bm, bn, tid); CP_COMMIT();
    load_stage(sm, 1, 1, bm, bn, tid); CP_COMMIT();

    for (int i = 0; i < NCH; i++) {
        const int s = i % NS;

        asm volatile("cp.async.wait_group 1;" ::: "memory");
        __syncthreads();   // stage i ready; stage (i+2)%NS free (chunk i-1 done)

        if (i + 2 < NCH) load_stage(sm, (i + 2) % NS, i + 2, bm, bn, tid);
        CP_COMMIT();

        const uint32_t* A = (const uint32_t*)(sm + s * STAGEF);
        const uint32_t* B = A + HALFST;
        const uint32_t* Ab = A + (wm * 64 + g) * ROWPAD + tig;
        const uint32_t* Bb = B + (wn * 64 + g) * ROWPAD + tig;

#pragma unroll
        for (int ks = 0; ks < 4; ks++) {
            uint32_t af[4][4], bf[8][2];
            const int ko = ks * 8;
#pragma unroll
            for (int ii = 0; ii < 4; ii++) {
                const uint32_t* p = Ab + ii * 16 * ROWPAD + ko;
                af[ii][0] = p[0];
                af[ii][1] = p[8 * ROWPAD];
                af[ii][2] = p[4];
                af[ii][3] = p[8 * ROWPAD + 4];
            }
#pragma unroll
            for (int jj = 0; jj < 8; jj++) {
                const uint32_t* p = Bb + jj * 8 * ROWPAD + ko;
                bf[jj][0] = p[0];
                bf[jj][1] = p[4];
            }
#pragma unroll
            for (int ii = 0; ii < 4; ii++)
#pragma unroll
                for (int jj = 0; jj < 8; jj++)
                    mma_tf32(acc[ii][jj], af[ii], bf[jj]);
        }
    }

    // epilogue: out[b][n][p];  m = wm*64 + ii*16 + g (+8), n = wn*64 + jj*8 + tig*2 (+1)
    const int b  = bm >> 12;
    const int p0 = (bm & (HWc - 1)) + wm * 64 + g;
    float* ob = out + ((size_t)b * OO << 12) + p0;
#pragma unroll
    for (int jj = 0; jj < 8; jj++) {
        const int n = bn + wn * 64 + jj * 8 + tig * 2;
        float* o0 = ob + ((size_t)n << 12);
        float* o1 = o0 + HWc;
#pragma unroll
        for (int ii = 0; ii < 4; ii++) {
            const int mo = ii * 16;
            o0[mo]     = acc[ii][jj][0];
            o1[mo]     = acc[ii][jj][1];
            o0[mo + 8] = acc[ii][jj][2];
            o1[mo + 8] = acc[ii][jj][3];
        }
    }
}

// ---------------------------------------------------------------------------
extern "C" void kernel_launch(void* const* d_in, const int* in_sizes, int n_in,
                              void* d_out, int out_size) {
    const float* x      = (const float*)d_in[0];
    const float* offset = (const float*)d_in[1];
    const float* mask   = (const float*)d_in[2];
    const float* weight = (const float*)d_in[3];
    float* out = (float*)d_out;

    cudaFuncSetAttribute(k_gemm_mma, cudaFuncAttributeMaxDynamicSharedMemorySize, GSMEM);

    k_transpose<<<dim3(HWc / 32, CC / 32, BB), dim3(32, 8)>>>(x);
    k_wt<<<(OO * KDIM) / 256, 256>>>(weight);
    k_im2col<<<(BB * KKc * HWc) / 4, 256>>>(offset, mask);
    k_gemm_mma<<<dim3(OO / 128, MDIM / 128), 128, GSMEM>>>(out);
}